// round 8
// baseline (speedup 1.0000x reference)
#include <cuda_runtime.h>
#include <cuda_bf16.h>
#include <cstdint>
#include <math.h>

#define Bk 32
#define Tk 400
#define Pk 3500
#define Sk 2000
#define Ek 50000
#define NCH 500
#define CHSZ 100
#define NTILEH 220            // 110 p-tiles x 2 batch halves
#define NUNIT (Sk + NTILEH)   // 2220 work units
#define KNORM 8
#define MAXBLK 256
#define NSB ((Sk + 15) / 16)  // 125 state blocks in the simple layout
#define ARCCAP 4224           // records fitting in the 33KB smem union

// ------------- device-global scratch (static, no runtime allocation) -------------
__device__ unsigned short d_alpha[2][Sk * Bk];   // bf16 bits
__device__ unsigned short d_ex[2][Pk * Bk];      // bf16 bits
__device__ float d_part[MAXBLK * Bk];
__device__ uint2 d_arcs[Ek];              // {src | pdf<<16, prob_bits}, dst-sorted
__device__ int   d_hist[Sk * NCH];        // transposed: [state][chunk]
__device__ int   d_base[Sk + 1];
__device__ int   d_totals[Sk];
__device__ unsigned d_bcount;             // 0 at rest
__device__ unsigned d_bgen;

__device__ __forceinline__ float bf2f(unsigned short u) {
    return __uint_as_float(((unsigned)u) << 16);
}
__device__ __forceinline__ unsigned short f2bf(float f) {
    return __bfloat16_as_ushort(__float2bfloat16(f));
}

// ================= setup: deterministic stable counting sort by dst ==============
__global__ void k_hist(const int* __restrict__ dst) {
    __shared__ int cnt[Sk];
    int c = blockIdx.x;
    for (int s = threadIdx.x; s < Sk; s += blockDim.x) cnt[s] = 0;
    __syncthreads();
    int e0 = c * CHSZ, e1 = min(Ek, e0 + CHSZ);
    for (int e = e0 + threadIdx.x; e < e1; e += blockDim.x) atomicAdd(&cnt[dst[e]], 1);
    __syncthreads();
    for (int s = threadIdx.x; s < Sk; s += blockDim.x) d_hist[s * NCH + c] = cnt[s];
}

__global__ void k_totals() {   // warp per state, coalesced within-state row
    int wid = threadIdx.x >> 5, lane = threadIdx.x & 31;
    int s = blockIdx.x * 8 + wid;
    if (s >= Sk) return;
    int sum = 0;
    for (int c = lane; c < NCH; c += 32) sum += d_hist[s * NCH + c];
    #pragma unroll
    for (int off = 16; off; off >>= 1) sum += __shfl_down_sync(0xFFFFFFFFu, sum, off);
    if (lane == 0) d_totals[s] = sum;
}

__global__ void k_scan() {  // 1 block, 1024 threads: exclusive scan totals -> base
    __shared__ int sm[1024];
    int tid = threadIdx.x;
    int a0 = (2 * tid     < Sk) ? d_totals[2 * tid]     : 0;
    int a1 = (2 * tid + 1 < Sk) ? d_totals[2 * tid + 1] : 0;
    sm[tid] = a0 + a1;
    __syncthreads();
    for (int d = 1; d < 1024; d <<= 1) {
        int v = sm[tid];
        int u = (tid >= d) ? sm[tid - d] : 0;
        __syncthreads();
        sm[tid] = v + u;
        __syncthreads();
    }
    int excl = tid ? sm[tid - 1] : 0;
    if (2 * tid     < Sk) d_base[2 * tid]     = excl;
    if (2 * tid + 1 < Sk) d_base[2 * tid + 1] = excl + a0;
    if (tid == 0) d_base[Sk] = sm[1023];
}

__global__ void k_off() {   // warp per state: exclusive scan of chunk counts
    int wid = threadIdx.x >> 5, lane = threadIdx.x & 31;
    int s = blockIdx.x * 8 + wid;
    if (s >= Sk) return;
    int run = d_base[s];
    for (int c0 = 0; c0 < NCH; c0 += 32) {
        int c = c0 + lane;
        int h = (c < NCH) ? d_hist[s * NCH + c] : 0;
        int inc = h;
        #pragma unroll
        for (int d = 1; d < 32; d <<= 1) {
            int n = __shfl_up_sync(0xFFFFFFFFu, inc, d);
            if (lane >= d) inc += n;
        }
        if (c < NCH) d_hist[s * NCH + c] = run + inc - h;
        run += __shfl_sync(0xFFFFFFFFu, inc, 31);
    }
}

__global__ void k_scatter(const int* __restrict__ src, const int* __restrict__ dst,
                          const int* __restrict__ pdf, const float* __restrict__ ltp) {
    __shared__ int offs[Sk];
    __shared__ int sdst[CHSZ];
    __shared__ uint2 srec[CHSZ];
    int c = blockIdx.x;
    for (int s = threadIdx.x; s < Sk; s += blockDim.x) offs[s] = d_hist[s * NCH + c];
    int e0 = c * CHSZ, e1 = min(Ek, e0 + CHSZ), n = e1 - e0;
    for (int i = threadIdx.x; i < n; i += blockDim.x) {
        int e = e0 + i;
        sdst[i] = dst[e];
        srec[i] = make_uint2((unsigned)src[e] | ((unsigned)pdf[e] << 16),
                             __float_as_uint(expf(ltp[e])));
    }
    __syncthreads();
    if (threadIdx.x == 0) {   // serial within chunk: stable + deterministic
        for (int i = 0; i < n; i++) {
            int d = sdst[i];
            d_arcs[offs[d]++] = srec[i];
        }
    }
}

// ============ grid barrier: single atomic counter, acquire/release, no fences =====
__device__ __forceinline__ void gbar(unsigned& g, int nblk, int tid) {
    __syncthreads();
    if (tid == 0) {
        unsigned gn = g + 1u;
        unsigned a;
        asm volatile("atom.add.release.gpu.u32 %0, [%1], %2;"
                     : "=r"(a) : "l"(&d_bcount), "r"(1u) : "memory");
        if (a == (unsigned)nblk - 1u) {
            asm volatile("st.relaxed.gpu.u32 [%0], %1;"
                         :: "l"(&d_bcount), "r"(0u) : "memory");
            asm volatile("st.release.gpu.u32 [%0], %1;"
                         :: "l"(&d_bgen), "r"(gn) : "memory");
        } else {
            unsigned cur;
            int spins = 0;
            while (true) {
                asm volatile("ld.acquire.gpu.u32 %0, [%1];"
                             : "=r"(cur) : "l"(&d_bgen) : "memory");
                if (cur == gn) break;
                __nanosleep((++spins > 1024) ? 64 : 20);
            }
        }
    }
    __syncthreads();
    g = g + 1u;
}

// exp(x) transpose half-tile: p rows [32j,32j+32), batch half h -> d_ex[buf]
__device__ __forceinline__ void ex_tile(int j, int h, int t, int buf,
                                        const float* __restrict__ x,
                                        float* tw, int lane) {
    int p0 = j * 32;
    int p = p0 + lane;
    bool pok = (p < Pk);
    #pragma unroll
    for (int bb = 0; bb < 16; bb++) {
        float v = pok ? x[(16 * h + bb) * (Tk * Pk) + t * Pk + p] : 0.0f;
        tw[bb * 33 + lane] = v;
    }
    __syncwarp();
    int b2 = lane & 15, pr = lane >> 4;
    #pragma unroll
    for (int k = 0; k < 16; k++) {
        int pp = 2 * k + pr;
        int pg = p0 + pp;
        if (pg < Pk)
            d_ex[buf][pg * 32 + 16 * h + b2] = f2bf(__expf(tw[b2 * 33 + pp]));
    }
    __syncwarp();
}

// arc gather pass: templated so smem vs global record pointers each specialize
template <typename AP>
__device__ __forceinline__ float arc_pass(AP ap, int b0, int b1,
                                          const unsigned short* __restrict__ aC,
                                          const unsigned short* __restrict__ eC,
                                          int lane) {
    float a0 = 0.f, a1 = 0.f, a2 = 0.f, a3 = 0.f;
    int i = b0;
    for (; i + 8 <= b1; i += 8) {
        uint2 r0 = ap[i],     r1 = ap[i + 1], r2 = ap[i + 2], r3 = ap[i + 3];
        uint2 r4 = ap[i + 4], r5 = ap[i + 5], r6 = ap[i + 6], r7 = ap[i + 7];
        unsigned short ua0 = __ldcg(&aC[(r0.x & 0xFFFF) * 32 + lane]);
        unsigned short ue0 = __ldcg(&eC[(r0.x >> 16)   * 32 + lane]);
        unsigned short ua1 = __ldcg(&aC[(r1.x & 0xFFFF) * 32 + lane]);
        unsigned short ue1 = __ldcg(&eC[(r1.x >> 16)   * 32 + lane]);
        unsigned short ua2 = __ldcg(&aC[(r2.x & 0xFFFF) * 32 + lane]);
        unsigned short ue2 = __ldcg(&eC[(r2.x >> 16)   * 32 + lane]);
        unsigned short ua3 = __ldcg(&aC[(r3.x & 0xFFFF) * 32 + lane]);
        unsigned short ue3 = __ldcg(&eC[(r3.x >> 16)   * 32 + lane]);
        unsigned short ua4 = __ldcg(&aC[(r4.x & 0xFFFF) * 32 + lane]);
        unsigned short ue4 = __ldcg(&eC[(r4.x >> 16)   * 32 + lane]);
        unsigned short ua5 = __ldcg(&aC[(r5.x & 0xFFFF) * 32 + lane]);
        unsigned short ue5 = __ldcg(&eC[(r5.x >> 16)   * 32 + lane]);
        unsigned short ua6 = __ldcg(&aC[(r6.x & 0xFFFF) * 32 + lane]);
        unsigned short ue6 = __ldcg(&eC[(r6.x >> 16)   * 32 + lane]);
        unsigned short ua7 = __ldcg(&aC[(r7.x & 0xFFFF) * 32 + lane]);
        unsigned short ue7 = __ldcg(&eC[(r7.x >> 16)   * 32 + lane]);
        a0 += __uint_as_float(r0.y) * (bf2f(ua0) * bf2f(ue0));
        a1 += __uint_as_float(r1.y) * (bf2f(ua1) * bf2f(ue1));
        a2 += __uint_as_float(r2.y) * (bf2f(ua2) * bf2f(ue2));
        a3 += __uint_as_float(r3.y) * (bf2f(ua3) * bf2f(ue3));
        a0 += __uint_as_float(r4.y) * (bf2f(ua4) * bf2f(ue4));
        a1 += __uint_as_float(r5.y) * (bf2f(ua5) * bf2f(ue5));
        a2 += __uint_as_float(r6.y) * (bf2f(ua6) * bf2f(ue6));
        a3 += __uint_as_float(r7.y) * (bf2f(ua7) * bf2f(ue7));
    }
    for (; i + 2 <= b1; i += 2) {
        uint2 r0 = ap[i], r1 = ap[i + 1];
        a0 += __uint_as_float(r0.y) *
              (bf2f(__ldcg(&aC[(r0.x & 0xFFFF) * 32 + lane])) *
               bf2f(__ldcg(&eC[(r0.x >> 16)   * 32 + lane])));
        a1 += __uint_as_float(r1.y) *
              (bf2f(__ldcg(&aC[(r1.x & 0xFFFF) * 32 + lane])) *
               bf2f(__ldcg(&eC[(r1.x >> 16)   * 32 + lane])));
    }
    if (i < b1) {
        uint2 r0 = ap[i];
        a0 += __uint_as_float(r0.y) *
              (bf2f(__ldcg(&aC[(r0.x & 0xFFFF) * 32 + lane])) *
               bf2f(__ldcg(&eC[(r0.x >> 16)   * 32 + lane])));
    }
    return (a0 + a1) + (a2 + a3);
}

// ============================ persistent main kernel =============================
__global__ __launch_bounds__(512, 1) void k_main(const float* __restrict__ x,
                                                 const float* __restrict__ initlp,
                                                 float* __restrict__ out, int nblk) {
    __shared__ float s_part[16 * 32];
    __shared__ float s_scale[32];
    __shared__ __align__(16) float s_mem[16 * 16 * 33];   // union: tiles OR arc cache

    const int tid = threadIdx.x, wid = tid >> 5, lane = tid & 31, blk = blockIdx.x;
    const int NW = nblk * 16;
    const int W = blk * 16 + wid;
    float* tw = s_mem + wid * (16 * 33);
    uint2* s_arcs = (uint2*)s_mem;

    unsigned g;
    asm volatile("ld.relaxed.gpu.u32 %0, [%1];" : "=r"(g) : "l"(&d_bgen) : "memory");

    const bool simple   = (NW >= NUNIT);                 // every warp has <=1 unit
    const bool hasState = simple ? (blk * 16 < Sk) : true;
    const int  npart    = simple ? NSB : nblk;           // blocks producing partials

    // ---- stage this block's arc records into smem (contiguous after dst-sort) ----
    bool staged = false;
    int sb0 = 0, sb1 = 0;
    if (simple && hasState) {
        int gbase0 = d_base[blk * 16];
        int gend   = d_base[blk * 16 + 16];   // blk*16+16 <= Sk always (125 blocks)
        int nA = gend - gbase0;
        if (nA <= ARCCAP) {
            for (int i = tid; i < nA; i += 512) s_arcs[i] = d_arcs[gbase0 + i];
            staged = true;
            sb0 = d_base[W] - gbase0;
            sb1 = d_base[W + 1] - gbase0;
        } else {
            sb0 = d_base[W];
            sb1 = d_base[W + 1];
        }
    }
    __syncthreads();

    // ---- init: alpha0 and ex slice for t=0 ----
    for (int u = W; u < NUNIT; u += NW) {
        if (u < Sk) d_alpha[0][u * 32 + lane] = f2bf(__expf(initlp[u]));
        else        ex_tile((u - Sk) >> 1, (u - Sk) & 1, 0, 0, x, tw, lane);
    }
    double logC = 0.0;
    gbar(g, nblk, tid);

    int cur = 0;
    for (int t = 0; t < Tk; t++) {
        const bool ev = (t % KNORM == 0) && (t > 0);
        const bool mkpart = ((t + 1) % KNORM == 0);

        if (hasState && ev) {
            // parallel reduction of the 125 per-block partials across 16 warps
            float c = 0.0f;
            for (int r = wid; r < npart; r += 16)
                c += __ldcg(&d_part[r * 32 + lane]);
            s_part[wid * 32 + lane] = c;
            __syncthreads();
            if (wid == 0) {
                float cs = 0.0f;
                #pragma unroll
                for (int k = 0; k < 16; k++) cs += s_part[k * 32 + lane];
                s_scale[lane] = (cs > 0.0f) ? (1.0f / cs) : 1.0f;
                if (blk == 0 && cs > 0.0f) logC += log((double)cs);
            }
            __syncthreads();
        }

        const unsigned short* aC = d_alpha[cur];
        unsigned short*       aN = d_alpha[cur ^ 1];
        const unsigned short* eC = d_ex[t & 1];
        float psum = 0.0f;
        const float sc = (hasState && ev) ? s_scale[lane] : 1.0f;

        for (int u = W; u < NUNIT; u += NW) {
            if (u < Sk) {
                float v;
                if (simple) {
                    v = staged ? arc_pass(s_arcs, sb0, sb1, aC, eC, lane)
                               : arc_pass((const uint2*)d_arcs, sb0, sb1, aC, eC, lane);
                } else {
                    v = arc_pass((const uint2*)d_arcs, d_base[u], d_base[u + 1], aC, eC, lane);
                }
                v *= sc;
                aN[u * 32 + lane] = f2bf(v);
                psum += v;
            } else if (t + 1 < Tk) {
                ex_tile((u - Sk) >> 1, (u - Sk) & 1, t + 1, (t + 1) & 1, x, tw, lane);
            }
        }

        if (mkpart && hasState) {
            s_part[wid * 32 + lane] = psum;
            __syncthreads();
            if (wid == 0) {
                float cs4 = 0.0f;
                #pragma unroll
                for (int k = 0; k < 16; k++) cs4 += s_part[k * 32 + lane];
                d_part[blk * 32 + lane] = cs4;
            }
        }

        gbar(g, nblk, tid);
        cur ^= 1;
    }

    // ---- final reduction: objf = mean_b (logC_b + log colsum_b) ----
    if (blk == 0 && wid == 0) {
        float cs = 0.0f;
        for (int r = 0; r < npart; r++) cs += __ldcg(&d_part[r * 32 + lane]);
        double tot = logC + log((double)cs);
        #pragma unroll
        for (int off = 16; off; off >>= 1)
            tot += __shfl_down_sync(0xFFFFFFFFu, tot, off);
        if (lane == 0) out[0] = (float)(tot / (double)Bk);
    }
}

// ================================== launcher =====================================
extern "C" void kernel_launch(void* const* d_in, const int* in_sizes, int n_in,
                              void* d_out, int out_size) {
    const float* x    = (const float*)d_in[0];
    const float* ltp  = (const float*)d_in[1];
    const float* init = (const float*)d_in[2];
    const int*   src  = (const int*)d_in[3];
    const int*   dst  = (const int*)d_in[4];
    const int*   pdf  = (const int*)d_in[5];
    float* out = (float*)d_out;

    int nblk = 0;
    cudaDeviceGetAttribute(&nblk, cudaDevAttrMultiProcessorCount, 0);
    if (nblk <= 0 || nblk > MAXBLK) nblk = 148;

    k_hist<<<NCH, 256>>>(dst);
    k_totals<<<(Sk + 7) / 8, 256>>>();
    k_scan<<<1, 1024>>>();
    k_off<<<(Sk + 7) / 8, 256>>>();
    k_scatter<<<NCH, 128>>>(src, dst, pdf, ltp);
    k_main<<<nblk, 512>>>(x, init, out, nblk);
}

// round 11
// speedup vs baseline: 1.0614x; 1.0614x over previous
#include <cuda_runtime.h>
#include <cuda_bf16.h>
#include <cstdint>
#include <math.h>

#define Bk 32
#define Tk 400
#define Pk 3500
#define Sk 2000
#define Ek 50000
#define NCH 500
#define CHSZ 100
#define NTILEH 220            // 110 p-tiles x 2 batch halves
#define NUNIT (Sk + NTILEH)   // 2220 work units
#define KNORM 8
#define MAXBLK 256
#define NSB ((Sk + 15) / 16)  // 125 state blocks in the simple layout
#define ARCCAP 4224           // records fitting in the 33KB smem union

// ------------- device-global scratch (static, no runtime allocation) -------------
__device__ float d_alpha[2][Sk * Bk];
__device__ float d_ex[2][Pk * Bk];
__device__ float d_part[MAXBLK * Bk];
__device__ uint2 d_arcs[Ek];              // {src | pdf<<16, prob_bits}, dst-sorted
__device__ int   d_hist[Sk * NCH];        // transposed: [state][chunk]
__device__ int   d_base[Sk + 1];
__device__ int   d_totals[Sk];
__device__ unsigned d_bcount;             // 0 at rest
__device__ unsigned d_bgen;

// ============ grid barrier: single atomic counter, acquire/release (PROVEN) ======
__device__ __forceinline__ void gbar(unsigned& g, int nblk, int tid) {
    __syncthreads();
    if (tid == 0) {
        unsigned gn = g + 1u;
        unsigned a;
        asm volatile("atom.add.release.gpu.u32 %0, [%1], %2;"
                     : "=r"(a) : "l"(&d_bcount), "r"(1u) : "memory");
        if (a == (unsigned)nblk - 1u) {
            asm volatile("st.relaxed.gpu.u32 [%0], %1;"
                         :: "l"(&d_bcount), "r"(0u) : "memory");
            asm volatile("st.release.gpu.u32 [%0], %1;"
                         :: "l"(&d_bgen), "r"(gn) : "memory");
        } else {
            unsigned cur;
            int spins = 0;
            while (true) {
                asm volatile("ld.acquire.gpu.u32 %0, [%1];"
                             : "=r"(cur) : "l"(&d_bgen) : "memory");
                if (cur == gn) break;
                __nanosleep((++spins > 2048) ? 64 : 20);
            }
        }
    }
    __syncthreads();
    g = g + 1u;
}

// ================= setup: deterministic stable counting sort by dst ==============
__global__ void k_hist(const int* __restrict__ dst) {
    __shared__ int cnt[Sk];
    int c = blockIdx.x;
    for (int s = threadIdx.x; s < Sk; s += blockDim.x) cnt[s] = 0;
    __syncthreads();
    int e0 = c * CHSZ, e1 = min(Ek, e0 + CHSZ);
    for (int e = e0 + threadIdx.x; e < e1; e += blockDim.x) atomicAdd(&cnt[dst[e]], 1);
    __syncthreads();
    for (int s = threadIdx.x; s < Sk; s += blockDim.x) d_hist[s * NCH + c] = cnt[s];
}

// totals + scan + offsets fused into one persistent kernel (2 internal barriers)
__global__ __launch_bounds__(256, 1) void k_mid(int nblk) {
    const int tid = threadIdx.x, wid = tid >> 5, lane = tid & 31, blk = blockIdx.x;
    const int gw = blk * 8 + wid;            // global warp id, 8 warps/block
    const int NWRP = nblk * 8;
    unsigned g;
    asm volatile("ld.relaxed.gpu.u32 %0, [%1];" : "=r"(g) : "l"(&d_bgen) : "memory");

    // ---- phase 1: per-state totals (warp per state, strided) ----
    for (int s = gw; s < Sk; s += NWRP) {
        int sum = 0;
        for (int c = lane; c < NCH; c += 32) sum += d_hist[s * NCH + c];
        #pragma unroll
        for (int off = 16; off; off >>= 1) sum += __shfl_down_sync(0xFFFFFFFFu, sum, off);
        if (lane == 0) d_totals[s] = sum;
    }
    gbar(g, nblk, tid);

    // ---- phase 2: exclusive scan of totals -> base (block 0 only) ----
    if (blk == 0) {
        __shared__ int ssum[256];
        int vals[8];
        int ts = 0;
        if (tid < Sk / 8) {
            #pragma unroll
            for (int j = 0; j < 8; j++) { vals[j] = d_totals[tid * 8 + j]; ts += vals[j]; }
        }
        ssum[tid] = ts;
        __syncthreads();
        for (int d = 1; d < 256; d <<= 1) {
            int v = ssum[tid];
            int u = (tid >= d) ? ssum[tid - d] : 0;
            __syncthreads();
            ssum[tid] = v + u;
            __syncthreads();
        }
        int pre = tid ? ssum[tid - 1] : 0;
        if (tid < Sk / 8) {
            int run = pre;
            #pragma unroll
            for (int j = 0; j < 8; j++) { d_base[tid * 8 + j] = run; run += vals[j]; }
        }
        if (tid == 255) d_base[Sk] = ssum[255];
    }
    gbar(g, nblk, tid);

    // ---- phase 3: per-state chunk-offset scan (warp per state, strided) ----
    for (int s = gw; s < Sk; s += NWRP) {
        int run = d_base[s];
        for (int c0 = 0; c0 < NCH; c0 += 32) {
            int c = c0 + lane;
            int h = (c < NCH) ? d_hist[s * NCH + c] : 0;
            int inc = h;
            #pragma unroll
            for (int d = 1; d < 32; d <<= 1) {
                int n = __shfl_up_sync(0xFFFFFFFFu, inc, d);
                if (lane >= d) inc += n;
            }
            if (c < NCH) d_hist[s * NCH + c] = run + inc - h;
            run += __shfl_sync(0xFFFFFFFFu, inc, 31);
        }
    }
}

__global__ void k_scatter(const int* __restrict__ src, const int* __restrict__ dst,
                          const int* __restrict__ pdf, const float* __restrict__ ltp) {
    __shared__ int offs[Sk];
    __shared__ int sdst[CHSZ];
    __shared__ uint2 srec[CHSZ];
    int c = blockIdx.x;
    for (int s = threadIdx.x; s < Sk; s += blockDim.x) offs[s] = d_hist[s * NCH + c];
    int e0 = c * CHSZ, e1 = min(Ek, e0 + CHSZ), n = e1 - e0;
    for (int i = threadIdx.x; i < n; i += blockDim.x) {
        int e = e0 + i;
        sdst[i] = dst[e];
        srec[i] = make_uint2((unsigned)src[e] | ((unsigned)pdf[e] << 16),
                             __float_as_uint(expf(ltp[e])));
    }
    __syncthreads();
    if (threadIdx.x == 0) {   // serial within chunk: stable + deterministic
        for (int i = 0; i < n; i++) {
            int d = sdst[i];
            d_arcs[offs[d]++] = srec[i];
        }
    }
}

// exp(x) transpose half-tile: p rows [32j,32j+32), batch half h -> d_ex[buf]
__device__ __forceinline__ void ex_tile(int j, int h, int t, int buf,
                                        const float* __restrict__ x,
                                        float* tw, int lane) {
    int p0 = j * 32;
    int p = p0 + lane;
    bool pok = (p < Pk);
    #pragma unroll
    for (int bb = 0; bb < 16; bb++) {
        float v = pok ? x[(16 * h + bb) * (Tk * Pk) + t * Pk + p] : 0.0f;
        tw[bb * 33 + lane] = v;
    }
    __syncwarp();
    int b2 = lane & 15, pr = lane >> 4;
    #pragma unroll
    for (int k = 0; k < 16; k++) {
        int pp = 2 * k + pr;
        int pg = p0 + pp;
        if (pg < Pk)
            d_ex[buf][pg * 32 + 16 * h + b2] = __expf(tw[b2 * 33 + pp]);
    }
    __syncwarp();
}

// arc gather pass: templated so smem vs global record pointers each specialize
template <typename AP>
__device__ __forceinline__ float arc_pass(AP ap, int b0, int b1,
                                          const float* __restrict__ aC,
                                          const float* __restrict__ eC, int lane) {
    float a0 = 0.f, a1 = 0.f, a2 = 0.f, a3 = 0.f;
    int i = b0;
    for (; i + 8 <= b1; i += 8) {
        uint2 r0 = ap[i],     r1 = ap[i + 1], r2 = ap[i + 2], r3 = ap[i + 3];
        uint2 r4 = ap[i + 4], r5 = ap[i + 5], r6 = ap[i + 6], r7 = ap[i + 7];
        float g0 = __ldcg(&aC[(r0.x & 0xFFFF) * 32 + lane]) * __ldcg(&eC[(r0.x >> 16) * 32 + lane]);
        float g1 = __ldcg(&aC[(r1.x & 0xFFFF) * 32 + lane]) * __ldcg(&eC[(r1.x >> 16) * 32 + lane]);
        float g2 = __ldcg(&aC[(r2.x & 0xFFFF) * 32 + lane]) * __ldcg(&eC[(r2.x >> 16) * 32 + lane]);
        float g3 = __ldcg(&aC[(r3.x & 0xFFFF) * 32 + lane]) * __ldcg(&eC[(r3.x >> 16) * 32 + lane]);
        float g4 = __ldcg(&aC[(r4.x & 0xFFFF) * 32 + lane]) * __ldcg(&eC[(r4.x >> 16) * 32 + lane]);
        float g5 = __ldcg(&aC[(r5.x & 0xFFFF) * 32 + lane]) * __ldcg(&eC[(r5.x >> 16) * 32 + lane]);
        float g6 = __ldcg(&aC[(r6.x & 0xFFFF) * 32 + lane]) * __ldcg(&eC[(r6.x >> 16) * 32 + lane]);
        float g7 = __ldcg(&aC[(r7.x & 0xFFFF) * 32 + lane]) * __ldcg(&eC[(r7.x >> 16) * 32 + lane]);
        a0 += __uint_as_float(r0.y) * g0;  a1 += __uint_as_float(r1.y) * g1;
        a2 += __uint_as_float(r2.y) * g2;  a3 += __uint_as_float(r3.y) * g3;
        a0 += __uint_as_float(r4.y) * g4;  a1 += __uint_as_float(r5.y) * g5;
        a2 += __uint_as_float(r6.y) * g6;  a3 += __uint_as_float(r7.y) * g7;
    }
    for (; i + 2 <= b1; i += 2) {
        uint2 r0 = ap[i], r1 = ap[i + 1];
        a0 += __uint_as_float(r0.y) *
              (__ldcg(&aC[(r0.x & 0xFFFF) * 32 + lane]) * __ldcg(&eC[(r0.x >> 16) * 32 + lane]));
        a1 += __uint_as_float(r1.y) *
              (__ldcg(&aC[(r1.x & 0xFFFF) * 32 + lane]) * __ldcg(&eC[(r1.x >> 16) * 32 + lane]));
    }
    if (i < b1) {
        uint2 r0 = ap[i];
        a0 += __uint_as_float(r0.y) *
              (__ldcg(&aC[(r0.x & 0xFFFF) * 32 + lane]) * __ldcg(&eC[(r0.x >> 16) * 32 + lane]));
    }
    return (a0 + a1) + (a2 + a3);
}

// ============================ persistent main kernel =============================
__global__ __launch_bounds__(512, 1) void k_main(const float* __restrict__ x,
                                                 const float* __restrict__ initlp,
                                                 float* __restrict__ out, int nblk) {
    __shared__ float s_part[16 * 32];
    __shared__ float s_scale[32];
    __shared__ __align__(16) float s_mem[16 * 16 * 33];   // union: tiles OR arc cache

    const int tid = threadIdx.x, wid = tid >> 5, lane = tid & 31, blk = blockIdx.x;
    const int NW = nblk * 16;
    const int W = blk * 16 + wid;
    float* tw = s_mem + wid * (16 * 33);
    uint2* s_arcs = (uint2*)s_mem;

    unsigned g;
    asm volatile("ld.relaxed.gpu.u32 %0, [%1];" : "=r"(g) : "l"(&d_bgen) : "memory");

    const bool simple   = (NW >= NUNIT);                 // every warp has <=1 unit
    const bool hasState = simple ? (blk * 16 < Sk) : true;
    const int  npart    = simple ? NSB : nblk;           // blocks producing partials

    // ---- stage this block's arc records into smem (contiguous after dst-sort) ----
    bool staged = false;
    int sb0 = 0, sb1 = 0;
    if (simple && hasState) {
        int gbase0 = d_base[blk * 16];
        int gend   = d_base[blk * 16 + 16];   // blk*16+16 <= Sk always (125 blocks)
        int nA = gend - gbase0;
        if (nA <= ARCCAP) {
            for (int i = tid; i < nA; i += 512) s_arcs[i] = d_arcs[gbase0 + i];
            staged = true;
            sb0 = d_base[W] - gbase0;
            sb1 = d_base[W + 1] - gbase0;
        } else {
            sb0 = d_base[W];
            sb1 = d_base[W + 1];
        }
    }
    __syncthreads();

    // ---- init: alpha0 and ex slice for t=0 ----
    for (int u = W; u < NUNIT; u += NW) {
        if (u < Sk) d_alpha[0][u * 32 + lane] = __expf(initlp[u]);
        else        ex_tile((u - Sk) >> 1, (u - Sk) & 1, 0, 0, x, tw, lane);
    }
    double logC = 0.0;
    gbar(g, nblk, tid);

    int cur = 0;
    for (int t = 0; t < Tk; t++) {
        const bool ev = (t % KNORM == 0) && (t > 0);
        const bool mkpart = ((t + 1) % KNORM == 0);

        if (hasState && ev) {
            // parallel reduction of the 125 per-block partials across 16 warps
            float c = 0.0f;
            for (int r = wid; r < npart; r += 16)
                c += __ldcg(&d_part[r * 32 + lane]);
            s_part[wid * 32 + lane] = c;
            __syncthreads();
            if (wid == 0) {
                float cs = 0.0f;
                #pragma unroll
                for (int k = 0; k < 16; k++) cs += s_part[k * 32 + lane];
                s_scale[lane] = (cs > 0.0f) ? (1.0f / cs) : 1.0f;
                if (blk == 0 && cs > 0.0f) logC += log((double)cs);
            }
            __syncthreads();
        }

        const float* aC = d_alpha[cur];
        float*       aN = d_alpha[cur ^ 1];
        const float* eC = d_ex[t & 1];
        float psum = 0.0f;
        const float sc = (hasState && ev) ? s_scale[lane] : 1.0f;

        for (int u = W; u < NUNIT; u += NW) {
            if (u < Sk) {
                float v;
                if (simple) {
                    v = staged ? arc_pass(s_arcs, sb0, sb1, aC, eC, lane)
                               : arc_pass((const uint2*)d_arcs, sb0, sb1, aC, eC, lane);
                } else {
                    v = arc_pass((const uint2*)d_arcs, d_base[u], d_base[u + 1], aC, eC, lane);
                }
                v *= sc;
                aN[u * 32 + lane] = v;
                psum += v;
            } else if (t + 1 < Tk) {
                ex_tile((u - Sk) >> 1, (u - Sk) & 1, t + 1, (t + 1) & 1, x, tw, lane);
            }
        }

        if (mkpart && hasState) {
            s_part[wid * 32 + lane] = psum;
            __syncthreads();
            if (wid == 0) {
                float cs4 = 0.0f;
                #pragma unroll
                for (int k = 0; k < 16; k++) cs4 += s_part[k * 32 + lane];
                d_part[blk * 32 + lane] = cs4;
            }
        }

        gbar(g, nblk, tid);
        cur ^= 1;
    }

    // ---- final reduction: objf = mean_b (logC_b + log colsum_b) ----
    if (blk == 0 && wid == 0) {
        float cs = 0.0f;
        for (int r = 0; r < npart; r++) cs += __ldcg(&d_part[r * 32 + lane]);
        double tot = logC + log((double)cs);
        #pragma unroll
        for (int off = 16; off; off >>= 1)
            tot += __shfl_down_sync(0xFFFFFFFFu, tot, off);
        if (lane == 0) out[0] = (float)(tot / (double)Bk);
    }
}

// ================================== launcher =====================================
extern "C" void kernel_launch(void* const* d_in, const int* in_sizes, int n_in,
                              void* d_out, int out_size) {
    const float* x    = (const float*)d_in[0];
    const float* ltp  = (const float*)d_in[1];
    const float* init = (const float*)d_in[2];
    const int*   src  = (const int*)d_in[3];
    const int*   dst  = (const int*)d_in[4];
    const int*   pdf  = (const int*)d_in[5];
    float* out = (float*)d_out;

    int nblk = 0;
    cudaDeviceGetAttribute(&nblk, cudaDevAttrMultiProcessorCount, 0);
    if (nblk <= 0 || nblk > MAXBLK) nblk = 148;

    k_hist<<<NCH, 256>>>(dst);
    k_mid<<<nblk, 256>>>(nblk);
    k_scatter<<<NCH, 128>>>(src, dst, pdf, ltp);
    k_main<<<nblk, 512>>>(x, init, out, nblk);
}